// round 8
// baseline (speedup 1.0000x reference)
#include <cuda_runtime.h>

#define NN 20000
#define BB 64
#define EE 1280000
#define TNB 625    // NN / 32 (exact)

// Scratch (allocation-free per rules). Globals start zeroed; the accT
// zero-invariant across graph replays is maintained by epilogue_kernel.
__device__ __align__(16) float g_xT[NN * BB];    // xT[n*64 + b]
__device__ __align__(16) float g_accT[NN * BB];  // accT[n*64 + b]
__device__ __align__(16) float g_v[EE];          // adj*w precomputed

// K1: smem-tiled transpose x[B,N] -> xT[N,B], 32n x 64b tiles, 512 threads
// (625 blocks ~ 4 CTAs/SM: best-measured latency hiding). No accT zeroing
// (moved to epilogue). Also precomputes g_v = adj*w for a slice of edges
// (2048 edges/block * 625 = EE exactly), hidden under the transpose latency.
__global__ void __launch_bounds__(512)
prep_kernel(const float* __restrict__ x,
            const float* __restrict__ adj,
            const float* __restrict__ w) {
    __shared__ float t[32][65];
    int tid = threadIdx.x;
    int n0 = blockIdx.x * 32;

    const float4* x4 = (const float4*)x;

    // Phase A: coalesced float4 reads along n. 64 b x 8 q = 512 items.
    {
        int b = tid >> 3, q = tid & 7;
        float4 v = x4[b * (NN / 4) + (n0 >> 2) + q];
        int nc = 4 * q;
        t[nc + 0][b] = v.x;
        t[nc + 1][b] = v.y;
        t[nc + 2][b] = v.z;
        t[nc + 3][b] = v.w;
    }

    // Edge-weight precompute: EE / TNB = 2048 edges per block, float4-wide.
    {
        const float4* adj4 = (const float4*)adj;
        const float4* w4   = (const float4*)w;
        float4*       v4   = (float4*)g_v;
        int e0 = blockIdx.x * 512;            // in float4 units (2048 floats)
        int i  = e0 + tid;
        float4 a = adj4[i], b4 = w4[i];
        v4[i] = make_float4(a.x * b4.x, a.y * b4.y, a.z * b4.z, a.w * b4.w);
    }
    __syncthreads();

    // Phase B: coalesced float4 writes along b into xT. 32 nc x 16 bq.
    {
        float4* xT4 = (float4*)g_xT;
        int nc = tid >> 4, bq = tid & 15;
        int n = n0 + nc;
        float4 v;
        v.x = t[nc][4 * bq + 0];
        v.y = t[nc][4 * bq + 1];
        v.z = t[nc][4 * bq + 2];
        v.w = t[nc][4 * bq + 3];
        xT4[n * 16 + bq] = v;
    }
}

// K2: edge scatter, half-warp per edge (at the LTS byte cap).
// Per edge: one LDG.128 gather from L2-resident xT + one red.global.add.v4.f32.
__global__ void scatter_kernel(const int* __restrict__ src,
                               const int* __restrict__ dst) {
    int g = (blockIdx.x * blockDim.x + threadIdx.x) >> 5;  // warp id
    int lane = threadIdx.x & 31;
    int e = g * 32 + lane;
    if (e >= EE) return;  // EE % 32 == 0: whole warp exits together

    int   s = src[e];
    int   d = dst[e];
    float v = g_v[e];

    int half = lane >> 4;
    int ll   = lane & 15;

    const float4* xT4 = (const float4*)g_xT;

    #pragma unroll 1
    for (int j = 0; j < 16; j++) {
        int sel = 2 * j + half;
        int   sj = __shfl_sync(0xffffffffu, s, sel);
        int   dj = __shfl_sync(0xffffffffu, d, sel);
        float vj = __shfl_sync(0xffffffffu, v, sel);

        float4 xv = xT4[sj * 16 + ll];           // LDG.128, coalesced, L2-hit
        float4 r;
        r.x = vj * xv.x;  r.y = vj * xv.y;
        r.z = vj * xv.z;  r.w = vj * xv.w;

        float* accp = &g_accT[dj * 64 + 4 * ll]; // 16B-aligned
        asm volatile("red.global.add.v4.f32 [%0], {%1, %2, %3, %4};"
                     :: "l"(accp), "f"(r.x), "f"(r.y), "f"(r.z), "f"(r.w)
                     : "memory");
    }
}

// K3: epilogue. Tile-transpose accT [N,B] -> out [B,N], 32n x 64b tiles,
// 512 threads. Re-zeros accT after reading (restores the replay invariant).
// out = relu(acc * (x[0,n]*self_w[n]) + bias[n]).
__global__ void __launch_bounds__(512)
epilogue_kernel(const float* __restrict__ x,
                const float* __restrict__ self_w,
                const float* __restrict__ bias,
                float* __restrict__ out) {
    __shared__ float tile[32][65];
    __shared__ float s_sl[32];
    __shared__ float s_b[32];
    int tid = threadIdx.x;
    int n0 = blockIdx.x * 32;

    // Load accT (float4 along b, L2-dirty hits) then zero it in place.
    {
        float4* acc4 = (float4*)g_accT;
        int nc = tid >> 4, bq = tid & 15;
        int n = n0 + nc;
        float4 v = acc4[n * 16 + bq];
        acc4[n * 16 + bq] = make_float4(0.f, 0.f, 0.f, 0.f);
        tile[nc][4 * bq + 0] = v.x;
        tile[nc][4 * bq + 1] = v.y;
        tile[nc][4 * bq + 2] = v.z;
        tile[nc][4 * bq + 3] = v.w;
    }
    if (tid < 32) {
        int n = n0 + tid;
        s_sl[tid] = x[n] * self_w[n];   // x[0, n] — faithful reference quirk
        s_b[tid]  = bias[n];
    }
    __syncthreads();

    // Store: coalesced float4 writes along n. 64 b x 8 q = 512 items.
    {
        float4* out4 = (float4*)out;
        int b = tid >> 3, q = tid & 7;
        int nc = 4 * q;
        float4 r;
        r.x = fmaxf(fmaf(tile[nc + 0][b], s_sl[nc + 0], s_b[nc + 0]), 0.f);
        r.y = fmaxf(fmaf(tile[nc + 1][b], s_sl[nc + 1], s_b[nc + 1]), 0.f);
        r.z = fmaxf(fmaf(tile[nc + 2][b], s_sl[nc + 2], s_b[nc + 2]), 0.f);
        r.w = fmaxf(fmaf(tile[nc + 3][b], s_sl[nc + 3], s_b[nc + 3]), 0.f);
        out4[b * (NN / 4) + (n0 >> 2) + q] = r;
    }
}

extern "C" void kernel_launch(void* const* d_in, const int* in_sizes, int n_in,
                              void* d_out, int out_size) {
    const float* x      = (const float*)d_in[0];
    const float* adj    = (const float*)d_in[1];
    const float* w      = (const float*)d_in[2];
    const float* self_w = (const float*)d_in[3];
    const float* bias   = (const float*)d_in[4];
    const int*   src    = (const int*)d_in[5];
    const int*   dst    = (const int*)d_in[6];
    float* out = (float*)d_out;

    prep_kernel<<<TNB, 512>>>(x, adj, w);
    scatter_kernel<<<EE / 256, 256>>>(src, dst);
    epilogue_kernel<<<TNB, 512>>>(x, self_w, bias, out);
}